// round 4
// baseline (speedup 1.0000x reference)
#include <cuda_runtime.h>
#include <cstdint>

#define ROW_LEN 2048
#define NTHREADS 256
#define NWARP (NTHREADS / 32)
#define VPT 8       // values per thread
#define K_TOP 64
#define FULLMASK 0xffffffffu
#define H0STRIDE 257   // padded per-warp hist stride (bank-conflict-free across warps)

// Monotone bijection: float -> uint32 such that float order == uint order.
__device__ __forceinline__ uint32_t f2u(float f) {
    uint32_t u = __float_as_uint(f);
    return (u & 0x80000000u) ? ~u : (u | 0x80000000u);
}
__device__ __forceinline__ float u2f(uint32_t u) {
    u = (u & 0x80000000u) ? (u & 0x7FFFFFFFu) : ~u;
    return __uint_as_float(u);
}

__global__ __launch_bounds__(NTHREADS)
void topk_softmax_kernel(const float* __restrict__ in, float* __restrict__ out) {
    const int row  = blockIdx.x;
    const int tid  = threadIdx.x;
    const int lane = tid & 31;
    const int wid  = tid >> 5;

    const float4* rp4 = reinterpret_cast<const float4*>(in + (size_t)row * ROW_LEN);
    float4*       op4 = reinterpret_cast<float4*>(out + (size_t)row * ROW_LEN);

    __shared__ int      hist0[NWARP * H0STRIDE];  // per-warp pass-0 histograms
    __shared__ int      hist1[256];               // shared hist for passes >= 1
    __shared__ int      s_wsum[NWARP];
    __shared__ uint32_t s_pref, s_vk;
    __shared__ int      s_k, s_cnt;
    __shared__ float    s_sum;

    // ---- 1. Load row; keep floats AND order-preserving uint keys ----
    float4 a = rp4[tid];
    float4 b = rp4[tid + NTHREADS];
    float v[VPT];
    v[0] = a.x; v[1] = a.y; v[2] = a.z; v[3] = a.w;
    v[4] = b.x; v[5] = b.y; v[6] = b.z; v[7] = b.w;
    uint32_t key[VPT];
    #pragma unroll
    for (int i = 0; i < VPT; i++) key[i] = f2u(v[i]);

    // ---- 2. Zero scratch (overlaps with global-load latency) ----
    #pragma unroll
    for (int i = tid; i < NWARP * H0STRIDE; i += NTHREADS) hist0[i] = 0;
    hist1[tid] = 0;
    if (tid == 0) s_sum = 0.0f;
    __syncthreads();                                         // B1

    // ---- 3. Pass 0: per-warp histogram on top byte ----
    int* myh = &hist0[wid * H0STRIDE];
    #pragma unroll
    for (int i = 0; i < VPT; i++)
        atomicAdd(&myh[key[i] >> 24], 1);
    __syncthreads();                                         // B2

    // combined bin count for this thread's bin
    int h = 0;
    #pragma unroll
    for (int w = 0; w < NWARP; w++) h += hist0[w * H0STRIDE + tid];

    // warp-level suffix sum, then cross-warp
    int s = h;
    #pragma unroll
    for (int o = 1; o < 32; o <<= 1) {
        int t = __shfl_down_sync(FULLMASK, s, o);
        if (lane + o < 32) s += t;
    }
    if (lane == 0) s_wsum[wid] = s;
    __syncthreads();                                         // B3
    int S = s;
    #pragma unroll
    for (int w = 1; w < NWARP; w++)
        if (w > wid) S += s_wsum[w];
    int Sn = S - h;
    if (S >= K_TOP && Sn < K_TOP) {                          // unique crossing thread
        s_pref = (uint32_t)tid << 24;
        s_k    = K_TOP - Sn;
        s_cnt  = h;
    }
    __syncthreads();                                         // B4

    // ---- 4. Passes 1..3 (generic), early exit when the bin holds 1 element ----
    int passn = 1;
    while (s_cnt > 1 && passn < 4) {
        if (passn > 1) {                 // re-zero (rare path)
            hist1[tid] = 0;
            __syncthreads();
        }
        const int      shift = 24 - passn * 8;
        const uint32_t pmask = 0xFFFFFFFFu << (shift + 8);
        const uint32_t pref  = s_pref;
        const int      kcur  = s_k;

        #pragma unroll
        for (int i = 0; i < VPT; i++)
            if ((key[i] & pmask) == pref)
                atomicAdd(&hist1[(key[i] >> shift) & 0xFF], 1);
        __syncthreads();

        int h1 = hist1[tid];
        int s1 = h1;
        #pragma unroll
        for (int o = 1; o < 32; o <<= 1) {
            int t = __shfl_down_sync(FULLMASK, s1, o);
            if (lane + o < 32) s1 += t;
        }
        if (lane == 0) s_wsum[wid] = s1;
        __syncthreads();
        int S1 = s1;
        #pragma unroll
        for (int w = 1; w < NWARP; w++)
            if (w > wid) S1 += s_wsum[w];
        int Sn1 = S1 - h1;
        if (S1 >= kcur && Sn1 < kcur) {
            s_pref = pref | ((uint32_t)tid << shift);
            s_k    = kcur - Sn1;
            s_cnt  = h1;
        }
        __syncthreads();
        passn++;
    }

    // ---- 5. Resolve the exact 64th-largest key ----
    const int shift_res = 32 - 8 * passn;   // bits below this are unresolved
    if (shift_res != 0) {
        // s_cnt == 1: the unique key with this prefix IS the k-th value
        const uint32_t fmask = 0xFFFFFFFFu << shift_res;
        const uint32_t pref  = s_pref;
        #pragma unroll
        for (int i = 0; i < VPT; i++)
            if ((key[i] & fmask) == pref) s_vk = key[i];
    } else if (tid == 0) {
        s_vk = s_pref;                        // fully resolved after 4 passes
    }
    __syncthreads();                                         // B_vk
    const uint32_t vk_u = s_vk;
    const float    c    = u2f(vk_u);          // softmax offset (shift-invariant)

    // ---- 6. Masked exp + sum (offset by vk; survivors in [1, e^(max-vk)]) ----
    float sum = 0.0f;
    #pragma unroll
    for (int i = 0; i < VPT; i++) {
        float ev = (key[i] >= vk_u) ? __expf(v[i] - c) : 0.0f;
        v[i] = ev;
        sum += ev;
    }
    #pragma unroll
    for (int o = 16; o; o >>= 1) sum += __shfl_xor_sync(FULLMASK, sum, o);
    if (lane == 0) atomicAdd(&s_sum, sum);
    __syncthreads();                                         // B_sum

    const float inv = __fdividef(1.0f, s_sum);

    // ---- 7. Store (coalesced float4) ----
    float4 o1 = make_float4(v[0] * inv, v[1] * inv, v[2] * inv, v[3] * inv);
    float4 o2 = make_float4(v[4] * inv, v[5] * inv, v[6] * inv, v[7] * inv);
    op4[tid]            = o1;
    op4[tid + NTHREADS] = o2;
}

extern "C" void kernel_launch(void* const* d_in, const int* in_sizes, int n_in,
                              void* d_out, int out_size) {
    const float* in  = (const float*)d_in[0];
    float*       out = (float*)d_out;
    const int nrows = in_sizes[0] / ROW_LEN;   // 2*16*2048 = 65536
    topk_softmax_kernel<<<nrows, NTHREADS>>>(in, out);
}

// round 5
// speedup vs baseline: 1.0007x; 1.0007x over previous
#include <cuda_runtime.h>
#include <cstdint>

#define ROW_LEN 2048
#define NTHREADS 256
#define NWARP (NTHREADS / 32)
#define VPT 8       // values per thread
#define K_TOP 64
#define FULLMASK 0xffffffffu
#define NCOPY 4        // sub-warp histogram copies (lane & 3)
#define CSTRIDE 257    // bank-offset stride between copies

// Monotone bijection: float -> uint32 such that float order == uint order.
__device__ __forceinline__ uint32_t f2u(float f) {
    uint32_t u = __float_as_uint(f);
    return (u & 0x80000000u) ? ~u : (u | 0x80000000u);
}
__device__ __forceinline__ float u2f(uint32_t u) {
    u = (u & 0x80000000u) ? (u & 0x7FFFFFFFu) : ~u;
    return __uint_as_float(u);
}

__global__ __launch_bounds__(NTHREADS)
void topk_softmax_kernel(const float* __restrict__ in, float* __restrict__ out) {
    const int row  = blockIdx.x;
    const int tid  = threadIdx.x;
    const int lane = tid & 31;
    const int wid  = tid >> 5;

    const float4* rp4 = reinterpret_cast<const float4*>(in + (size_t)row * ROW_LEN);
    float4*       op4 = reinterpret_cast<float4*>(out + (size_t)row * ROW_LEN);

    __shared__ int      hist0[NCOPY * CSTRIDE];   // pass-0: 4 sub-warp copies
    __shared__ int      hist1[256];               // passes >= 1: single copy
    __shared__ int      s_wsum[NWARP];
    __shared__ uint32_t s_pref, s_vk;
    __shared__ int      s_k, s_cnt;
    __shared__ float    s_sum;

    // ---- 1. Issue loads, zero scratch while they are in flight ----
    float4 a = rp4[tid];
    float4 b = rp4[tid + NTHREADS];

    hist0[tid]       = 0;
    hist0[tid + 256] = 0;
    hist0[tid + 512] = 0;
    hist0[tid + 768] = 0;
    if (tid < NCOPY * CSTRIDE - 1024) hist0[tid + 1024] = 0;
    hist1[tid] = 0;
    if (tid == 0) s_sum = 0.0f;

    float v[VPT];
    v[0] = a.x; v[1] = a.y; v[2] = a.z; v[3] = a.w;
    v[4] = b.x; v[5] = b.y; v[6] = b.z; v[7] = b.w;
    uint32_t key[VPT];
    #pragma unroll
    for (int i = 0; i < VPT; i++) key[i] = f2u(v[i]);
    __syncthreads();                                         // B1

    // ---- 2. Pass 0: histogram on top byte, 4 sub-warp copies ----
    int* myh = &hist0[(lane & (NCOPY - 1)) * CSTRIDE];
    #pragma unroll
    for (int i = 0; i < VPT; i++)
        atomicAdd(&myh[key[i] >> 24], 1);
    __syncthreads();                                         // B2

    // combine copies for this thread's bin
    int h = hist0[tid] + hist0[tid + CSTRIDE]
          + hist0[tid + 2 * CSTRIDE] + hist0[tid + 3 * CSTRIDE];

    // suffix scan: S = count of keys with top byte >= tid
    int s = h;
    #pragma unroll
    for (int o = 1; o < 32; o <<= 1) {
        int t = __shfl_down_sync(FULLMASK, s, o);
        if (lane + o < 32) s += t;
    }
    if (lane == 0) s_wsum[wid] = s;
    __syncthreads();                                         // B3
    int S = s;
    #pragma unroll
    for (int w = 1; w < NWARP; w++)
        if (w > wid) S += s_wsum[w];
    const int Sn = S - h;
    if (S >= K_TOP && Sn < K_TOP) {                          // unique crossing thread
        s_pref = (uint32_t)tid << 24;
        s_k    = K_TOP - Sn;
        s_cnt  = h;
    }
    __syncthreads();                                         // B4

    // ---- 3. Passes 1..3, early exit when candidate bin holds 1 element ----
    int passn = 1;
    while (s_cnt > 1 && passn < 4) {
        const int      shift = 24 - passn * 8;
        const uint32_t pmask = 0xFFFFFFFFu << (shift + 8);
        const uint32_t pref  = s_pref;
        const int      kcur  = s_k;

        #pragma unroll
        for (int i = 0; i < VPT; i++)
            if ((key[i] & pmask) == pref)
                atomicAdd(&hist1[(key[i] >> shift) & 0xFF], 1);
        __syncthreads();                                     // B5

        const int h1 = hist1[tid];
        hist1[tid] = 0;            // each thread re-zeros only its own bin: no race
        int s1 = h1;
        #pragma unroll
        for (int o = 1; o < 32; o <<= 1) {
            int t = __shfl_down_sync(FULLMASK, s1, o);
            if (lane + o < 32) s1 += t;
        }
        if (lane == 0) s_wsum[wid] = s1;
        __syncthreads();                                     // B6
        int S1 = s1;
        #pragma unroll
        for (int w = 1; w < NWARP; w++)
            if (w > wid) S1 += s_wsum[w];
        const int Sn1 = S1 - h1;
        if (S1 >= kcur && Sn1 < kcur) {
            s_pref = pref | ((uint32_t)tid << shift);
            s_k    = kcur - Sn1;
            s_cnt  = h1;
        }
        __syncthreads();                                     // B7
        passn++;
    }

    // ---- 4. Resolve the exact 64th-largest key ----
    const int shift_res = 32 - 8 * passn;   // bits below this are unresolved
    if (shift_res != 0) {
        // s_cnt == 1: the unique key carrying this prefix IS the k-th value
        const uint32_t fmask = 0xFFFFFFFFu << shift_res;
        const uint32_t pref  = s_pref;
        #pragma unroll
        for (int i = 0; i < VPT; i++)
            if ((key[i] & fmask) == pref) s_vk = key[i];
    } else if (tid == 0) {
        s_vk = s_pref;                        // fully resolved after 4 passes
    }
    __syncthreads();                                         // B_vk
    const uint32_t vk_u = s_vk;
    const float    c    = u2f(vk_u);          // softmax offset (shift-invariant)

    // ---- 5. Masked exp + sum ----
    float sum = 0.0f;
    #pragma unroll
    for (int i = 0; i < VPT; i++) {
        float ev = (key[i] >= vk_u) ? __expf(v[i] - c) : 0.0f;
        v[i] = ev;
        sum += ev;
    }
    #pragma unroll
    for (int o = 16; o; o >>= 1) sum += __shfl_xor_sync(FULLMASK, sum, o);
    if (lane == 0) atomicAdd(&s_sum, sum);
    __syncthreads();                                         // B_sum

    const float inv = __fdividef(1.0f, s_sum);

    // ---- 6. Store (coalesced float4) ----
    float4 o1 = make_float4(v[0] * inv, v[1] * inv, v[2] * inv, v[3] * inv);
    float4 o2 = make_float4(v[4] * inv, v[5] * inv, v[6] * inv, v[7] * inv);
    op4[tid]            = o1;
    op4[tid + NTHREADS] = o2;
}

extern "C" void kernel_launch(void* const* d_in, const int* in_sizes, int n_in,
                              void* d_out, int out_size) {
    const float* in  = (const float*)d_in[0];
    float*       out = (float*)d_out;
    const int nrows = in_sizes[0] / ROW_LEN;   // 2*16*2048 = 65536
    topk_softmax_kernel<<<nrows, NTHREADS>>>(in, out);
}

// round 6
// speedup vs baseline: 1.1494x; 1.1487x over previous
#include <cuda_runtime.h>
#include <cstdint>

#define ROW_LEN 2048
#define NTHREADS 256
#define NWARP 8
#define VPT 8
#define K_TOP 64
#define NBINS 2048
#define FSCALE 224.0f
#define FBIAS  1024.0f
#define FULLMASK 0xffffffffu

__device__ __forceinline__ int bin_of(float x) {
    int b = (int)fmaf(x, FSCALE, FBIAS);      // trunc; monotone nondecreasing
    return min(max(b, 0), NBINS - 1);
}

__global__ __launch_bounds__(NTHREADS)
void topk_softmax_kernel(const float* __restrict__ in, float* __restrict__ out) {
    const int tid  = threadIdx.x;
    const int lane = tid & 31;
    const int wid  = tid >> 5;
    const size_t rbase = (size_t)blockIdx.x * ROW_LEN;

    const float4* rp4 = reinterpret_cast<const float4*>(in + rbase);
    float4*       op4 = reinterpret_cast<float4*>(out + rbase);

    __shared__ int   hist[NBINS];        // reused as candidate float buffer later
    __shared__ int   s_wsum[NWARP];
    __shared__ int   s_bin, s_kc, s_cnt;
    __shared__ float s_vk, s_sum;

    // ---- 1. Issue loads; zero histogram while they're in flight ----
    float4 a = rp4[tid];
    float4 b = rp4[tid + NTHREADS];
    reinterpret_cast<int4*>(hist)[tid]            = make_int4(0, 0, 0, 0);
    reinterpret_cast<int4*>(hist)[tid + NTHREADS] = make_int4(0, 0, 0, 0);
    if (tid == 0) { s_cnt = 0; s_sum = 0.0f; }

    float v[VPT];
    v[0] = a.x; v[1] = a.y; v[2] = a.z; v[3] = a.w;
    v[4] = b.x; v[5] = b.y; v[6] = b.z; v[7] = b.w;
    __syncthreads();                                          // B1

    // ---- 2. Single value-domain histogram (2048 uniform bins) ----
    #pragma unroll
    for (int i = 0; i < VPT; i++)
        atomicAdd(&hist[bin_of(v[i])], 1);
    __syncthreads();                                          // B2

    // ---- 3. Suffix scan over bins; locate crossing bin ----
    // thread t owns bins [8t, 8t+8); higher tid = higher value
    int4 h0 = reinterpret_cast<int4*>(hist)[tid * 2];
    int4 h1 = reinterpret_cast<int4*>(hist)[tid * 2 + 1];
    int hh[8] = { h0.x, h0.y, h0.z, h0.w, h1.x, h1.y, h1.z, h1.w };
    int lsum = 0;
    #pragma unroll
    for (int i = 0; i < 8; i++) lsum += hh[i];

    int s = lsum;                                 // warp suffix incl. self
    #pragma unroll
    for (int o = 1; o < 32; o <<= 1) {
        int t = __shfl_down_sync(FULLMASK, s, o);
        if (lane + o < 32) s += t;
    }
    if (lane == 0) s_wsum[wid] = s;
    __syncthreads();                                          // B3

    int T = s - lsum;                             // count in bins strictly above my chunk
    #pragma unroll
    for (int w = 1; w < NWARP; w++)
        if (w > wid) T += s_wsum[w];

    if (T < K_TOP && T + lsum >= K_TOP) {         // unique thread owns the crossing
        int suf = T;
        #pragma unroll
        for (int i = 7; i >= 0; i--) {
            int nsuf = suf + hh[i];
            if (suf < K_TOP && nsuf >= K_TOP) {
                s_bin = tid * 8 + i;
                s_kc  = K_TOP - suf;              // rank within bin, from the top
            }
            suf = nsuf;
        }
    }
    __syncthreads();                                          // B4 (hist reads done)

    // ---- 4. Compact the crossing bin's elements into smem ----
    const int bstar = s_bin;
    const int kc    = s_kc;
    // membership test: fma result in [b*, b*+1) (with open ends at clamp bins)
    const float flo = (bstar == 0)         ? -__int_as_float(0x7f800000) : (float)bstar;
    const float fhi = (bstar == NBINS - 1) ?  __int_as_float(0x7f800000) : (float)(bstar + 1);
    float* cand = reinterpret_cast<float*>(hist);
    #pragma unroll
    for (int i = 0; i < VPT; i++) {
        float f = fmaf(v[i], FSCALE, FBIAS);      // identical FMA as bin_of
        if (f >= flo && f < fhi) {
            int idx = atomicAdd(&s_cnt, 1);
            cand[idx] = v[i];
        }
    }
    __syncthreads();                                          // B5

    // ---- 5. Warp 0: exact kc-th largest among candidates (tie-robust) ----
    if (wid == 0) {
        const int c = s_cnt;                      // >= kc, usually 1-3
        int   remaining = kc;
        float bound = __int_as_float(0x7f800000); // +inf
        float vk;
        for (;;) {
            float m = -__int_as_float(0x7f800000);
            for (int i = lane; i < c; i += 32) {
                float x = cand[i];
                if (x < bound) m = fmaxf(m, x);
            }
            #pragma unroll
            for (int o = 16; o; o >>= 1) m = fmaxf(m, __shfl_xor_sync(FULLMASK, m, o));
            int cnt = 0;
            for (int i = lane; i < c; i += 32) cnt += (cand[i] == m);
            #pragma unroll
            for (int o = 16; o; o >>= 1) cnt += __shfl_xor_sync(FULLMASK, cnt, o);
            if (cnt >= remaining) { vk = m; break; }
            remaining -= cnt;
            bound = m;
        }
        if (lane == 0) s_vk = vk;
    }
    __syncthreads();                                          // B6

    // ---- 6. Masked exp + sum (offset by vk; softmax is shift-invariant) ----
    const float vk = s_vk;
    float sum = 0.0f;
    #pragma unroll
    for (int i = 0; i < VPT; i++) {
        float ev = (v[i] >= vk) ? __expf(v[i] - vk) : 0.0f;
        v[i] = ev;
        sum += ev;
    }
    #pragma unroll
    for (int o = 16; o; o >>= 1) sum += __shfl_xor_sync(FULLMASK, sum, o);
    if (lane == 0) atomicAdd(&s_sum, sum);
    __syncthreads();                                          // B7

    const float inv = __fdividef(1.0f, s_sum);

    // ---- 7. Store (coalesced float4) ----
    float4 o1 = make_float4(v[0] * inv, v[1] * inv, v[2] * inv, v[3] * inv);
    float4 o2 = make_float4(v[4] * inv, v[5] * inv, v[6] * inv, v[7] * inv);
    op4[tid]            = o1;
    op4[tid + NTHREADS] = o2;
}

extern "C" void kernel_launch(void* const* d_in, const int* in_sizes, int n_in,
                              void* d_out, int out_size) {
    const float* in  = (const float*)d_in[0];
    float*       out = (float*)d_out;
    const int nrows = in_sizes[0] / ROW_LEN;   // 2*16*2048 = 65536
    topk_softmax_kernel<<<nrows, NTHREADS>>>(in, out);
}